// round 12
// baseline (speedup 1.0000x reference)
#include <cuda_runtime.h>
#include <math.h>

// Problem constants (fixed by the reference).
#define BB 8
#define CC 16
#define NNDIM 512
#define EE 1024
#define POS_PER_B    (NNDIM * NNDIM)        // 262,144
#define GROUPS_PER_B (POS_PER_B / 4)        // 65,536 float4 groups per batch
#define SLOTS 55                            // blocks per batch
#define PBLK (BB * SLOTS)                   // 440 blocks total (one wave)
#define BSTRIDE (SLOTS * 256)               // 14,080 groups
#define HASH_SZ 4096

// Globals (no dynamic allocation; g_done static-init + self-resetting).
__device__ float g_psum[PBLK];
__device__ float g_pcnt[PBLK];
__device__ unsigned int g_done = 0;

// ---------------------------------------------------------------------------
// Single fused kernel.
//  Block i: batch b = i & 7, slot bb = i >> 3 (0..54).
//  Streaming: groups g = bb*256 + t + k*14080 while g < 65536 (static; the
//  hot loop contains ONLY loads + math — no syncs, no atomics, no shared).
//  Per iteration: 16 class float4 loads staged in registers (MLP_p1=16,
//  __ldcs evict-first), log-sum-exp with label 0 folded as  log(sum) - x0,
//  masked accumulate into per-thread registers.
//  Corr: the bb==54 block of each batch (4 streaming iterations vs 5 for
//  bb<36, so it has slack) additionally dedups the batch's 1024 edges
//  (O(E) shared hash, last-write-wins via atomicMax on edge index) and
//  accumulates (x_class0 - x_attr) at masked-valid cells.
//  Retirement: one block reduction -> per-block partial (plain stores, no
//  init needed), ticket; winner block finalizes in parallel and resets the
//  ticket counter for the next graph replay.
// ---------------------------------------------------------------------------
__global__ void __launch_bounds__(256, 3) fused_kernel(
        const float* __restrict__ adj,
        const unsigned char* __restrict__ mask,
        const int* __restrict__ edge_index,
        const int* __restrict__ edge_attr,
        float* __restrict__ out) {
    const int t    = threadIdx.x;
    const int lane = t & 31, warp = t >> 5;
    const int b    = blockIdx.x & (BB - 1);
    const int bb   = blockIdx.x >> 3;        // 0..54 slot within batch

    __shared__ int   s_slotkey[HASH_SZ];     // corr hash (bb==54 only)
    __shared__ int   s_slotval[HASH_SZ];
    __shared__ float r_sum[8];
    __shared__ float r_cnt[8];
    __shared__ int   s_win;
    __shared__ double s_fs[BB];
    __shared__ double s_fc[BB];

    const float* adj_b = adj + (size_t)b * CC * POS_PER_B;
    const unsigned char* mask_b = mask + (size_t)b * POS_PER_B;

    float sum = 0.0f, cnt = 0.0f;

    // ---- edge-label correction (slot 54 only; hides in its 4-iter slack) ----
    if (bb == SLOTS - 1) {
        #pragma unroll
        for (int i = t; i < HASH_SZ; i += 256) {
            s_slotkey[i] = -1;
            s_slotval[i] = -1;
        }
        __syncthreads();
        const int2* ei = reinterpret_cast<const int2*>(edge_index) + (size_t)b * EE;
        int key[4], attr[4];
        unsigned hh[4];
        #pragma unroll
        for (int j = 0; j < 4; j++) {
            const int e = t + j * 256;
            const int2 rc = ei[e];
            key[j]  = (rc.x << 9) | rc.y;
            attr[j] = edge_attr[b * EE + e];
            unsigned h = (((unsigned)key[j] * 2654435761u) >> 20) & (HASH_SZ - 1);
            while (true) {
                int old = atomicCAS(&s_slotkey[h], -1, key[j]);
                if (old == -1 || old == key[j]) { atomicMax(&s_slotval[h], e); break; }
                h = (h + 1) & (HASH_SZ - 1);
            }
            hh[j] = h;
        }
        __syncthreads();
        #pragma unroll
        for (int j = 0; j < 4; j++) {
            const int e = t + j * 256;
            if (s_slotval[hh[j]] == e && attr[j] != 0) {     // live, nonzero
                const int r = key[j] >> 9, c = key[j] & (NNDIM - 1);
                const int cell = r * NNDIM + c;
                if (mask_b[cell]) {
                    const float* p = adj_b + cell;
                    sum += p[0] - p[(size_t)attr[j] * POS_PER_B];  // x0 -> xa
                }
            }
        }
    }

    // ---- streaming: static stride, pure loads+math hot loop ----
    for (int g = bb * 256 + t; g < GROUPS_PER_B; g += BSTRIDE) {
        const float4* base = reinterpret_cast<const float4*>(adj_b + (g << 2));
        const uchar4 m4 = *reinterpret_cast<const uchar4*>(mask_b + (g << 2));

        // phase 1: batched loads (16 independent LDG.128)
        float4 v[CC];
        #pragma unroll
        for (int c = 0; c < CC; c++)
            v[c] = __ldcs(base + (size_t)c * (POS_PER_B / 4));

        // phase 2: exp / accumulate
        float s0 = __expf(v[0].x), s1 = __expf(v[0].y);
        float s2 = __expf(v[0].z), s3 = __expf(v[0].w);
        #pragma unroll
        for (int c = 1; c < CC; c++) {
            s0 += __expf(v[c].x); s1 += __expf(v[c].y);
            s2 += __expf(v[c].z); s3 += __expf(v[c].w);
        }
        if (m4.x) { sum += __logf(s0) - v[0].x; cnt += 1.0f; }
        if (m4.y) { sum += __logf(s1) - v[0].y; cnt += 1.0f; }
        if (m4.z) { sum += __logf(s2) - v[0].z; cnt += 1.0f; }
        if (m4.w) { sum += __logf(s3) - v[0].w; cnt += 1.0f; }
    }

    // ---- retirement: single block reduction -> per-block partial ----
    #pragma unroll
    for (int off = 16; off > 0; off >>= 1) {
        sum += __shfl_down_sync(0xFFFFFFFFu, sum, off);
        cnt += __shfl_down_sync(0xFFFFFFFFu, cnt, off);
    }
    if (lane == 0) { r_sum[warp] = sum; r_cnt[warp] = cnt; }
    __syncthreads();

    if (t == 0) {
        float bs = 0.0f, bc = 0.0f;
        #pragma unroll
        for (int w = 0; w < 8; w++) { bs += r_sum[w]; bc += r_cnt[w]; }
        g_psum[blockIdx.x] = bs;              // plain stores (no init needed)
        g_pcnt[blockIdx.x] = bc;
        __threadfence();
        const unsigned ticket = atomicAdd(&g_done, 1u);
        s_win = (ticket == PBLK - 1) ? 1 : 0;
    }
    __syncthreads();

    // ---- winner block: parallel finalize + ticket reset ----
    if (s_win) {
        if (t < BB) { s_fs[t] = 0.0; s_fc[t] = 0.0; }
        __syncthreads();
        volatile float* vp = g_psum;
        volatile float* vc = g_pcnt;
        #pragma unroll
        for (int j = 0; j < 2; j++) {
            const int i = t + j * 256;
            if (i < PBLK) {
                atomicAdd(&s_fs[i & (BB - 1)], (double)vp[i]);
                atomicAdd(&s_fc[i & (BB - 1)], (double)vc[i]);
            }
        }
        __syncthreads();
        if (t == 0) {
            double acc = 0.0;
            #pragma unroll
            for (int i = 0; i < BB; i++) {
                double c = s_fc[i];
                if (c < 1.0) c = 1.0;
                acc += s_fs[i] / c;
            }
            out[0] = (float)(acc / (double)BB);
            g_done = 0u;                      // reset for next graph replay
        }
    }
}

// ---------------------------------------------------------------------------
// kernel_launch — inputs (metadata order): adj f32 [B,C,N,N], mask bool(u8)
// [B,N,N], edge_index i32 [B,E,2], edge_attr i32 [B,E]. Output: 1 fp32 scalar.
// ---------------------------------------------------------------------------
extern "C" void kernel_launch(void* const* d_in, const int* in_sizes, int n_in,
                              void* d_out, int out_size) {
    const float*         adj        = (const float*)d_in[0];
    const unsigned char* mask       = (const unsigned char*)d_in[1];
    const int*           edge_index = (const int*)d_in[2];
    const int*           edge_attr  = (const int*)d_in[3];
    float*               out        = (float*)d_out;

    fused_kernel<<<PBLK, 256>>>(adj, mask, edge_index, edge_attr, out);
}